// round 15
// baseline (speedup 1.0000x reference)
#include <cuda_runtime.h>
#include <cuda_fp16.h>
#include <cstdint>

// UnionLayer via degree-4 minimax polynomial -> fp16 mma.sync GEMM.
//   -log(1-t) ~= c0 + c1 t + c2 t^2 + c3 t^3 + c4 t^4   on t in [0, 0.5]
//   (degree-5 Chebyshev truncation minus the k=5 component; abs err ~ +-7e-5,
//    oscillating -> largely cancels over the d-sum)
//   c0 = 5.196e-5, c1 = 0.995072, c2 = 0.572809, c3 = -0.025378, c4 = 0.887357
//   S[b,nh] = 512*c0 + sum_n c_n * (u^n . w^n)  == GEMM, K = 4*512
//   con: u = 1-x, y = 1/(1+S);  dis: u = x, y = 1 - 1/(1+S)
// R15 = R14 mainloop (term-level software-pipelined register fragments, 256 thr,
// 8 warps: 4 m-slices x 2 d-halves) with NTERMS 5 -> 4 (-20% MMAs, -25% chains).
// B chain ratio factors r_n = c_{n+1}/c_n; c1, 512*c0 fold into epilogue FMA.
// Grid (8, 8, 2) = 128 CTAs.

#define DDIM    512
#define NOUT    512
#define NCOLS   256
#define NTERMS  4
#define MTILE   128
#define NTILE   32
#define THREADS 256

// chain ratios r_n = c_{n+1}/c_n (kf[0] unused)
#define R1   0.575646f
#define R2  -0.0443078f
#define R3 -34.9657f
// epilogue: S = C1E * acc + C0E
#define C1E  0.995072f
#define C0E  0.0266046f    // 512 * c0

__device__ __forceinline__ void mma16816(float* c, uint32_t a0, uint32_t a1,
                                         uint32_t a2, uint32_t a3,
                                         uint32_t b0, uint32_t b1) {
    asm volatile(
        "mma.sync.aligned.m16n8k16.row.col.f32.f16.f16.f32 "
        "{%0,%1,%2,%3}, {%4,%5,%6,%7}, {%8,%9}, {%0,%1,%2,%3};"
        : "+f"(c[0]), "+f"(c[1]), "+f"(c[2]), "+f"(c[3])
        : "r"(a0), "r"(a1), "r"(a2), "r"(a3), "r"(b0), "r"(b1));
}

__device__ __forceinline__ uint32_t h2u(__half2 h) {
    return *reinterpret_cast<uint32_t*>(&h);
}

__global__ __launch_bounds__(THREADS) void union_mma_kernel(
    const float* __restrict__ x,
    const float* __restrict__ Wcon,
    const float* __restrict__ Wdis,
    float* __restrict__ out)
{
    __shared__ float red[4][32][32];   // d-half-1 partials (16 KB)

    const int tid  = threadIdx.x;
    const int wid  = tid >> 5;
    const int lane = tid & 31;
    const int g    = lane >> 2;        // 0..7
    const int t4   = lane & 3;         // 0..3
    const int msl  = wid & 3;          // m-slice (32 rows)
    const int dh   = wid >> 2;         // d-half 0/1
    const int bn0  = blockIdx.x * NTILE;
    const int bm0  = blockIdx.y * MTILE;
    const int z    = blockIdx.z;       // 0 = con, 1 = dis
    const float* __restrict__ W = z ? Wdis : Wcon;

    const float* __restrict__ pA = &x[(bm0 + msl * 32 + g) * DDIM + dh * 256 + 2 * t4];
    const float* __restrict__ pB = &W[(bn0 + g) * DDIM + dh * 256 + 2 * t4];

    float acc[2][4][4];
#pragma unroll
    for (int mt = 0; mt < 2; mt++)
#pragma unroll
        for (int nt = 0; nt < 4; nt++)
#pragma unroll
            for (int c = 0; c < 4; c++) acc[mt][nt][c] = 0.0f;

    const float kf[NTERMS] = {0.f, R1, R2, R3};
    const int stag = msl * 4;          // per-warp unit-order stagger

    // staged raw for one 16-d unit: [row][pair]  (pair p -> d offset p*8 + {0,1})
    float2 sA[4][2], sB[4][2];
    {
        int off = ((0 + stag) & 15) * 16;
#pragma unroll
        for (int r = 0; r < 4; r++)
#pragma unroll
            for (int p = 0; p < 2; p++) {
                sA[r][p] = *reinterpret_cast<const float2*>(pA + r * 8 * DDIM + off + p * 8);
                sB[r][p] = *reinterpret_cast<const float2*>(pB + r * 8 * DDIM + off + p * 8);
            }
    }

#pragma unroll 1
    for (int u = 0; u < 16; u++) {
        // ---- build bases + term-1 fragments (buffer 0) ----
        __half2 baseA[4][2], baseB[4][2], curA[2][4][2], curB[2][4][2];
#pragma unroll
        for (int r = 0; r < 4; r++)
#pragma unroll
            for (int p = 0; p < 2; p++) {
                float ux = sA[r][p].x, uy = sA[r][p].y;
                if (z == 0) { ux = 1.0f - ux; uy = 1.0f - uy; }
                baseA[r][p]   = __floats2half2_rn(ux, uy);
                baseB[r][p]   = __floats2half2_rn(sB[r][p].x, sB[r][p].y);
                curA[0][r][p] = baseA[r][p];
                curB[0][r][p] = baseB[r][p];
            }

        // ---- prefetch next unit's raw (consumed next iteration) ----
        if (u + 1 < 16) {
            int off = ((u + 1 + stag) & 15) * 16;
#pragma unroll
            for (int r = 0; r < 4; r++)
#pragma unroll
                for (int p = 0; p < 2; p++) {
                    sA[r][p] = *reinterpret_cast<const float2*>(pA + r * 8 * DDIM + off + p * 8);
                    sB[r][p] = *reinterpret_cast<const float2*>(pB + r * 8 * DDIM + off + p * 8);
                }
        }

        // ---- 4 poly terms, software-pipelined: chain(n+1) BEFORE mma(n) ----
#pragma unroll
        for (int n = 0; n < NTERMS; n++) {
            const int cb = n & 1, nb = (n + 1) & 1;
            if (n + 1 < NTERMS) {
                const __half2 kfh = __float2half2_rn(kf[n + 1]);
#pragma unroll
                for (int r = 0; r < 4; r++)
#pragma unroll
                    for (int p = 0; p < 2; p++) {
                        curA[nb][r][p] = __hmul2(curA[cb][r][p], baseA[r][p]);
                        __half2 bb     = __hmul2(baseB[r][p], kfh);     // independent
                        curB[nb][r][p] = __hmul2(curB[cb][r][p], bb);   // 1 dependent link
                    }
            }
#pragma unroll
            for (int mt = 0; mt < 2; mt++) {
                uint32_t a0 = h2u(curA[cb][mt * 2 + 0][0]);
                uint32_t a1 = h2u(curA[cb][mt * 2 + 1][0]);
                uint32_t a2 = h2u(curA[cb][mt * 2 + 0][1]);
                uint32_t a3 = h2u(curA[cb][mt * 2 + 1][1]);
#pragma unroll
                for (int nt = 0; nt < 4; nt++) {
                    mma16816(acc[mt][nt], a0, a1, a2, a3,
                             h2u(curB[cb][nt][0]), h2u(curB[cb][nt][1]));
                }
            }
        }
    }

    // ---- merge d-halves: half 1 stores, half 0 adds + epilogue ----
    if (dh == 1) {
#pragma unroll
        for (int mt = 0; mt < 2; mt++)
#pragma unroll
            for (int hh = 0; hh < 2; hh++) {
                int r = mt * 16 + hh * 8 + g;
#pragma unroll
                for (int nt = 0; nt < 4; nt++) {
                    *reinterpret_cast<float2*>(&red[msl][r][nt * 8 + 2 * t4]) =
                        make_float2(acc[mt][nt][hh * 2 + 0], acc[mt][nt][hh * 2 + 1]);
                }
            }
    }
    __syncthreads();

    if (dh == 0) {
#pragma unroll
        for (int mt = 0; mt < 2; mt++) {
#pragma unroll
            for (int hh = 0; hh < 2; hh++) {
                int r = mt * 16 + hh * 8 + g;
                int m = bm0 + msl * 32 + r;
#pragma unroll
                for (int nt = 0; nt < 4; nt++) {
                    float2 o = *reinterpret_cast<const float2*>(&red[msl][r][nt * 8 + 2 * t4]);
                    float S0 = fmaf(C1E, acc[mt][nt][hh * 2 + 0] + o.x, C0E);
                    float S1 = fmaf(C1E, acc[mt][nt][hh * 2 + 1] + o.y, C0E);
                    float y0 = 1.0f / (1.0f + S0);
                    float y1 = 1.0f / (1.0f + S1);
                    if (z) { y0 = 1.0f - y0; y1 = 1.0f - y1; }
                    int col = bn0 + nt * 8 + 2 * t4;
                    *reinterpret_cast<float2*>(&out[m * NOUT + z * NCOLS + col]) =
                        make_float2(y0, y1);
                }
            }
        }
    }
}

extern "C" void kernel_launch(void* const* d_in, const int* in_sizes, int n_in,
                              void* d_out, int out_size)
{
    const float* x    = (const float*)d_in[0];
    const float* Wcon = (const float*)d_in[1];
    const float* Wdis = (const float*)d_in[2];
    float* out = (float*)d_out;

    dim3 grid(NCOLS / NTILE, 1024 / MTILE, 2);   // (8, 8, 2) = 128 CTAs
    union_mma_kernel<<<grid, THREADS>>>(x, Wcon, Wdis, out);
}